// round 16
// baseline (speedup 1.0000x reference)
#include <cuda_runtime.h>
#include <cuda_fp16.h>
#include <math.h>
#include <stdint.h>

#define RR 64
#define DT_C 0.1f
#define TAU_MIN_C 0.1f
#define TAU_MAX_C 10.0f
#define SCALING_C 2.0f          // 128/64

#define MAX_M 16384
#define MAX_O 4096
#define MAX_D 4096

// scratch (device globals: no allocation allowed)
__device__ __align__(16) __half g_hB[MAX_O * RR];     // fp16 of 2*hidden,
                                                      // PRE-SWIZZLED per 128-row tile:
                                                      // byte = (o>>7)*16384 + sw128((o&127)*128 + 2*c)
__device__ __align__(16) __half g_At[RR * MAX_D];     // A fp16, tiled+preswizzled
__device__ int g_liq_done;                            // liquid completion counter

// ---------------------------------------------------------------------------
// helpers
// ---------------------------------------------------------------------------
__device__ __forceinline__ uint32_t smem_u32(const void* p) {
    uint32_t a;
    asm("{ .reg .u64 t; cvta.to.shared.u64 t, %1; cvt.u32.u64 %0, t; }"
        : "=r"(a) : "l"(p));
    return a;
}
__device__ __forceinline__ uint32_t sw128(uint32_t o) { return o ^ ((o >> 3) & 0x70); }

__device__ __forceinline__ void ldm_x4(uint32_t* r, uint32_t addr) {
    asm volatile("ldmatrix.sync.aligned.m8n8.x4.shared.b16 {%0,%1,%2,%3}, [%4];"
                 : "=r"(r[0]), "=r"(r[1]), "=r"(r[2]), "=r"(r[3]) : "r"(addr));
}
// 1D bulk copy gmem->smem, completes on mbarrier (UBLKCP.S.G)
__device__ __forceinline__ void cp_bulk(uint32_t smem_dst, const void* gsrc,
                                        uint32_t bytes, uint32_t mbar) {
    asm volatile(
        "cp.async.bulk.shared::cluster.global.mbarrier::complete_tx::bytes "
        "[%0], [%1], %2, [%3];"
        :: "r"(smem_dst), "l"(gsrc), "r"(bytes), "r"(mbar) : "memory");
}
#define MBAR_INIT(mbar, cnt) \
    asm volatile("mbarrier.init.shared.b64 [%0], %1;" :: "r"(mbar), "r"((uint32_t)(cnt)) : "memory")
#define MBAR_EXPECT_TX(mbar, bytes) \
    asm volatile("mbarrier.arrive.expect_tx.shared.b64 _, [%0], %1;" \
                 :: "r"(mbar), "r"((uint32_t)(bytes)) : "memory")
#define MBAR_WAIT(mbar, parity) do { \
    asm volatile("{\n\t.reg .pred P1;\n\t" \
        "WAIT_%=:\n\t" \
        "mbarrier.try_wait.parity.acquire.cta.shared::cta.b64 P1, [%0], %1, 0x989680;\n\t" \
        "@P1 bra.uni DONE_%=;\n\t" \
        "bra.uni WAIT_%=;\n\t" \
        "DONE_%=:\n\t}" \
        :: "r"(mbar), "r"((uint32_t)(parity)) : "memory"); \
} while (0)

// D += A * B, fp16 inputs, fp32 accum
__device__ __forceinline__ void mma16816(float* d, const uint32_t* a, const uint32_t* b) {
    asm volatile(
        "mma.sync.aligned.m16n8k16.row.col.f32.f16.f16.f32 "
        "{%0,%1,%2,%3}, {%4,%5,%6,%7}, {%8,%9}, {%0,%1,%2,%3};"
        : "+f"(d[0]), "+f"(d[1]), "+f"(d[2]), "+f"(d[3])
        : "r"(a[0]), "r"(a[1]), "r"(a[2]), "r"(a[3]), "r"(b[0]), "r"(b[1]));
}
__device__ __forceinline__ uint32_t packH(float a, float b) {
    __half2 h = __floats2half2_rn(a, b);
    return *reinterpret_cast<uint32_t*>(&h);
}

// ---------------------------------------------------------------------------
// Kernel 0: repack lora_A fp32 -> g_At fp16 (per-K-tile 8KB blocks, SW128
// pre-applied) + reset the liquid completion flag for this replay.
// ---------------------------------------------------------------------------
__global__ __launch_bounds__(256) void convA_kernel(const float* __restrict__ A, int D)
{
    if (blockIdx.x == 0 && threadIdx.x == 0) g_liq_done = 0;
    int i = blockIdx.x * 256 + threadIdx.x;          // 0 .. 64*(D/8)-1
    int ncol = D >> 3;
    if (i < 64 * ncol) {
        int r = i / ncol, kch = i % ncol;
        int kt = kch >> 3, c16 = kch & 7;
        const float4* s = (const float4*)(A + (size_t)r * D + kch * 8);
        float4 v0 = s[0], v1 = s[1];
        uint4 w;
        w.x = packH(v0.x, v0.y);
        w.y = packH(v0.z, v0.w);
        w.z = packH(v1.x, v1.y);
        w.w = packH(v1.z, v1.w);
        *(uint4*)((char*)g_At + kt * 8192 + sw128((uint32_t)(r * 128 + c16 * 16))) = w;
    }
}

// ---------------------------------------------------------------------------
// Fused persistent kernel (128 threads / 4 warps):
//   blocks [0, nG1): GEMM1 t = x @ A^T (bulk 2-stage ring) -> t kept in smem
//       -> spin for liquid -> OUT-PHASE: o-loop of 32 x 128-o tiles,
//       B via single 16KB contiguous bulk per tile (2-stage mbar ring),
//       out = t @ Bh^T written directly. No g_t, no second GEMM kernel.
//   blocks [nG1, nG1+NLIQ): liquid dynamics; writes g_hB pre-swizzled,
//       then fence + atomic flag.
// ---------------------------------------------------------------------------
#define XSTRIDE 72                       // floats per x smem row (288 B)
#define X_BYTES (64 * XSTRIDE * 4)       // 18432
#define A_BYTES 8192
#define STAGE_BYTES (X_BYTES + A_BYTES)  // 26624
#define STAGE_TX    (64 * 256 + A_BYTES) // 24576 expected tx bytes
#define NLIQ 64
#define B_TILE 16384                     // 128 rows x 128 B

__global__ __launch_bounds__(128, 4) void fusedAll(
    const float* __restrict__ x,
    const float* __restrict__ lora_B, const float* __restrict__ hidden0,
    const float* __restrict__ W_gate, const float* __restrict__ b_gate,
    const float* __restrict__ W_tau,  const float* __restrict__ b_tau,
    float* __restrict__ out,
    int M, int D, int O, int nG1)
{
    extern __shared__ char dsm[];
    __shared__ __align__(8) uint64_t s_mbar[4];
    uint32_t sa  = smem_u32(dsm);
    uint32_t pad = (1024u - (sa & 1023u)) & 1023u;
    char*    bp  = dsm + pad;            // generic pointer, 1024-aligned
    uint32_t sb  = sa + pad;             // shared-space address, 1024-aligned
    int tid = threadIdx.x, wid = tid >> 5, lane = tid & 31;

    if ((int)blockIdx.x < nG1) {
        // ================= GEMM1: 64(M) x 64(N), K-tiles 64 ==================
        int warp_m = wid >> 1, warp_n = wid & 1;
        int tt = lane >> 3, rr = lane & 7;
        int g4 = lane >> 2, tq = lane & 3;
        int tc = tq * 2;

        int m0 = blockIdx.x * 64;
        uint32_t mb0 = smem_u32(&s_mbar[0]);
        uint32_t mb1 = smem_u32(&s_mbar[1]);
        uint32_t mbB0 = smem_u32(&s_mbar[2]);
        uint32_t mbB1 = smem_u32(&s_mbar[3]);

        int b_row  = warp_n * 32 + (tt >> 1) * 8 + rr;
        int b_colb = (tt & 1) * 16;

        float acc[2][4][4];
        #pragma unroll
        for (int i = 0; i < 2; i++)
            #pragma unroll
            for (int j = 0; j < 4; j++)
                #pragma unroll
                for (int k = 0; k < 4; k++) acc[i][j][k] = 0.0f;

        int nkt = D >> 6;

        if (tid == 0) {
            MBAR_INIT(mb0, 1); MBAR_INIT(mb1, 1);
            MBAR_INIT(mbB0, 1); MBAR_INIT(mbB1, 1);
        }
        __syncthreads();

        auto issue = [&](int kt, int slot, uint32_t mbar) {
            if (lane == 0) {
                uint32_t st = sb + slot * STAGE_BYTES;
                if (wid == 0) {
                    MBAR_EXPECT_TX(mbar, STAGE_TX);
                    cp_bulk(st + X_BYTES, (const char*)g_At + (size_t)kt * 8192,
                            A_BYTES, mbar);
                }
                int r0 = wid * 16;
                #pragma unroll
                for (int r = 0; r < 16; r++)
                    cp_bulk(st + (r0 + r) * (XSTRIDE * 4),
                            x + (size_t)(m0 + r0 + r) * D + kt * 64,
                            256, mbar);
            }
        };

        issue(0, 0, mb0);
        issue(1, 1, mb1);

        int fr = warp_m * 32 + g4;
        for (int kt = 0; kt < nkt; kt++) {
            int slot = kt & 1;
            uint32_t mbar = slot ? mb1 : mb0;
            MBAR_WAIT(mbar, (kt >> 1) & 1);

            const float* xs = (const float*)(bp + slot * STAGE_BYTES);
            uint32_t     at = sb + slot * STAGE_BYTES + X_BYTES;

            #pragma unroll
            for (int kk = 0; kk < 4; kk++) {
                uint32_t bh[4][2];
                #pragma unroll
                for (int np = 0; np < 2; np++) {
                    uint32_t off = sw128((uint32_t)((b_row + np * 16) * 128 + b_colb + kk * 32));
                    uint32_t r4[4];
                    ldm_x4(r4, at + off);
                    bh[2*np][0] = r4[0]; bh[2*np][1] = r4[1];
                    bh[2*np+1][0] = r4[2]; bh[2*np+1][1] = r4[3];
                }
                uint32_t ax[2][4];
                #pragma unroll
                for (int mt = 0; mt < 2; mt++) {
                    const float* p = xs + (fr + mt * 16) * XSTRIDE + tc + kk * 16;
                    float2 v0 = *(const float2*)(p);
                    float2 v1 = *(const float2*)(p + 8 * XSTRIDE);
                    float2 v2 = *(const float2*)(p + 8);
                    float2 v3 = *(const float2*)(p + 8 * XSTRIDE + 8);
                    ax[mt][0] = packH(v0.x, v0.y);
                    ax[mt][1] = packH(v1.x, v1.y);
                    ax[mt][2] = packH(v2.x, v2.y);
                    ax[mt][3] = packH(v3.x, v3.y);
                }
                #pragma unroll
                for (int mt = 0; mt < 2; mt++)
                    #pragma unroll
                    for (int nt = 0; nt < 4; nt++)
                        mma16816(acc[mt][nt], ax[mt], bh[nt]);
            }

            __syncthreads();
            if (kt + 2 < nkt)
                issue(kt + 2, slot, mbar);
        }

        // ---- t tile (64 x 64 fp16) -> smem at sb, SW128 layout -------------
        uint32_t tb = sb;
        #pragma unroll
        for (int mt = 0; mt < 2; mt++) {
            int mloc = warp_m * 32 + mt * 16 + g4;
            #pragma unroll
            for (int nt = 0; nt < 4; nt++) {
                int n = warp_n * 32 + nt * 8 + 2 * tq;
                *(uint32_t*)(dsm + pad + sw128((uint32_t)(mloc * 128 + 2 * n)))
                    = packH(acc[mt][nt][0], acc[mt][nt][1]);
                *(uint32_t*)(dsm + pad + sw128((uint32_t)((mloc + 8) * 128 + 2 * n)))
                    = packH(acc[mt][nt][2], acc[mt][nt][3]);
            }
        }

        // ---- wait for liquid (g_hB) --------------------------------------
        if (tid == 0) {
            int v;
            do {
                asm volatile("ld.acquire.gpu.global.b32 %0, [%1];"
                             : "=r"(v) : "l"(&g_liq_done) : "memory");
            } while (v < NLIQ);
        }
        __syncthreads();   // t-STS + flag both settled

        // ================= OUT-PHASE: out[m0..+63, :] = t @ Bh^T ============
        // warps 2(m) x 2(n): warp tile 32m x 64n. B stages at sb+8192/+24576.
        uint32_t bst0 = sb + 8192, bst1 = sb + 24576;
        int b2_row  = warp_n * 64 + (tt >> 1) * 8 + rr;

        auto issueB = [&](int ot) {
            if (tid == 0) {
                uint32_t mb = (ot & 1) ? mbB1 : mbB0;
                MBAR_EXPECT_TX(mb, B_TILE);
                cp_bulk((ot & 1) ? bst1 : bst0,
                        (const char*)g_hB + (size_t)ot * B_TILE, B_TILE, mb);
            }
        };
        issueB(0);
        issueB(1);

        int nOT = O >> 7;                 // 32
        int a_row = warp_m * 32 + (tt & 1) * 8 + rr;
        int a_colb = (tt >> 1) * 16;

        #pragma unroll 1
        for (int ot = 0; ot < nOT; ot++) {
            uint32_t bs = (ot & 1) ? bst1 : bst0;
            MBAR_WAIT((ot & 1) ? mbB1 : mbB0, (ot >> 1) & 1);

            float oacc[2][8][4];
            #pragma unroll
            for (int i = 0; i < 2; i++)
                #pragma unroll
                for (int j = 0; j < 8; j++)
                    #pragma unroll
                    for (int k = 0; k < 4; k++) oacc[i][j][k] = 0.0f;

            #pragma unroll
            for (int kk = 0; kk < 4; kk++) {
                uint32_t bh[8][2];
                #pragma unroll
                for (int np = 0; np < 4; np++) {
                    uint32_t off = sw128((uint32_t)((b2_row + np * 16) * 128 + b_colb + kk * 32));
                    uint32_t r4[4];
                    ldm_x4(r4, bs + off);
                    bh[2*np][0] = r4[0]; bh[2*np][1] = r4[1];
                    bh[2*np+1][0] = r4[2]; bh[2*np+1][1] = r4[3];
                }
                #pragma unroll
                for (int mt = 0; mt < 2; mt++) {
                    uint32_t ath[4];
                    uint32_t off = sw128((uint32_t)((a_row + mt * 16) * 128 + a_colb + kk * 32));
                    ldm_x4(ath, tb + off);
                    #pragma unroll
                    for (int nt = 0; nt < 8; nt++)
                        mma16816(oacc[mt][nt], ath, bh[nt]);
                }
            }

            #pragma unroll
            for (int mt = 0; mt < 2; mt++) {
                int m = m0 + warp_m * 32 + mt * 16 + g4;
                #pragma unroll
                for (int nt = 0; nt < 8; nt++) {
                    int o = ot * 128 + warp_n * 64 + nt * 8 + 2 * tq;
                    *(float2*)(out + (size_t)m * O + o)       = make_float2(oacc[mt][nt][0], oacc[mt][nt][1]);
                    *(float2*)(out + (size_t)(m + 8) * O + o) = make_float2(oacc[mt][nt][2], oacc[mt][nt][3]);
                }
            }
            __syncthreads();              // all reads of stage done
            if (ot + 2 < nOT) issueB(ot + 2);
        }
    } else {
        // ================= liquid path (4 warps per block) ===================
        float* WT2 = (float*)(bp);           // [64][132] = 33792 B
        for (int idx = tid; idx < 128 * 64; idx += 128) {
            int r = idx >> 6, k2 = idx & 63;
            if (r < 64) WT2[k2 * 132 + r]             = W_gate[r * 128 + 64 + k2];
            else        WT2[k2 * 132 + 64 + (r - 64)] = W_tau[(r - 64) * 128 + 64 + k2];
        }
        __syncthreads();

        int lb = blockIdx.x - nG1;                   // 0..NLIQ-1
        int gw = lb * 4 + wid;                       // 0..255
        int rows_per_warp = O / (NLIQ * 4);          // 16
        int base = gw * rows_per_warp;

        float bg0 = b_gate[lane], bg1 = b_gate[lane + 32];
        float bt0 = b_tau[lane],  bt1 = b_tau[lane + 32];

        for (int p = 0; p < rows_per_warp / 4; p++) {
            int o4 = base + p * 4;
            float tg0[4], tg1[4], h0[4], h1[4];
            #pragma unroll
            for (int j = 0; j < 4; j++) {
                tg0[j] = lora_B[(size_t)(o4 + j) * RR + lane];
                tg1[j] = lora_B[(size_t)(o4 + j) * RR + lane + 32];
                h0[j]  = hidden0[(size_t)(o4 + j) * RR + lane];
                h1[j]  = hidden0[(size_t)(o4 + j) * RR + lane + 32];
            }

            float pg0[4], pg1[4], pt0[4], pt1[4];
            #pragma unroll
            for (int j = 0; j < 4; j++) { pg0[j] = bg0; pg1[j] = bg1; pt0[j] = bt0; pt1[j] = bt1; }
            #pragma unroll 2
            for (int k0 = 0; k0 < 32; k0 += 4) {
                float4 wg0A = *(const float4*)(W_gate + lane * 128 + k0);
                float4 wg1A = *(const float4*)(W_gate + (lane + 32) * 128 + k0);
                float4 wt0A = *(const float4*)(W_tau  + lane * 128 + k0);
                float4 wt1A = *(const float4*)(W_tau  + (lane + 32) * 128 + k0);
                float4 wg0B = *(const float4*)(W_gate + lane * 128 + 32 + k0);
                float4 wg1B = *(const float4*)(W_gate + (lane + 32) * 128 + 32 + k0);
                float4 wt0B = *(const float4*)(W_tau  + lane * 128 + 32 + k0);
                float4 wt1B = *(const float4*)(W_tau  + (lane + 32) * 128 + 32 + k0);
                #pragma unroll
                for (int e = 0; e < 4; e++) {
                    float g0 = ((const float*)&wg0A)[e], g1 = ((const float*)&wg1A)[e];
                    float t0 = ((const float*)&wt0A)[e], t1 = ((const float*)&wt1A)[e];
                    float g0b = ((const float*)&wg0B)[e], g1b = ((const float*)&wg1B)[e];
                    float t0b = ((const float*)&wt0B)[e], t1b = ((const float*)&wt1B)[e];
                    #pragma unroll
                    for (int j = 0; j < 4; j++) {
                        float v  = __shfl_sync(0xffffffffu, tg0[j], k0 + e);
                        float v2 = __shfl_sync(0xffffffffu, tg1[j], k0 + e);
                        pg0[j] += v * g0;   pg1[j] += v * g1;
                        pt0[j] += v * t0;   pt1[j] += v * t1;
                        pg0[j] += v2 * g0b; pg1[j] += v2 * g1b;
                        pt0[j] += v2 * t0b; pt1[j] += v2 * t1b;
                    }
                }
            }

            #pragma unroll
            for (int step = 0; step < 3; step++) {
                float ga0[4], ga1[4], ta0[4], ta1[4];
                #pragma unroll
                for (int j = 0; j < 4; j++) { ga0[j] = pg0[j]; ga1[j] = pg1[j]; ta0[j] = pt0[j]; ta1[j] = pt1[j]; }
                #pragma unroll 8
                for (int k = 0; k < 32; k++) {
                    float wg0 = WT2[k * 132 + lane],      wg1 = WT2[k * 132 + lane + 32];
                    float wt0 = WT2[k * 132 + 64 + lane], wt1 = WT2[k * 132 + 96 + lane];
                    float wg0b = WT2[(32 + k) * 132 + lane],      wg1b = WT2[(32 + k) * 132 + lane + 32];
                    float wt0b = WT2[(32 + k) * 132 + 64 + lane], wt1b = WT2[(32 + k) * 132 + 96 + lane];
                    #pragma unroll
                    for (int j = 0; j < 4; j++) {
                        float v  = __shfl_sync(0xffffffffu, h0[j], k);
                        float v2 = __shfl_sync(0xffffffffu, h1[j], k);
                        ga0[j] += v * wg0;  ga1[j] += v * wg1;
                        ta0[j] += v * wt0;  ta1[j] += v * wt1;
                        ga0[j] += v2 * wg0b; ga1[j] += v2 * wg1b;
                        ta0[j] += v2 * wt0b; ta1[j] += v2 * wt1b;
                    }
                }
                #pragma unroll
                for (int j = 0; j < 4; j++) {
                    float f0   = 1.0f / (1.0f + expf(-ga0[j]));
                    float f1   = 1.0f / (1.0f + expf(-ga1[j]));
                    float tau0 = TAU_MIN_C + (TAU_MAX_C - TAU_MIN_C) / (1.0f + expf(-ta0[j]));
                    float tau1 = TAU_MIN_C + (TAU_MAX_C - TAU_MIN_C) / (1.0f + expf(-ta1[j]));
                    float a0   = 1.0f / tau0 + f0;
                    float a1   = 1.0f / tau1 + f1;
                    float d0   = expf(-a0 * DT_C);
                    float d1   = expf(-a1 * DT_C);
                    h0[j] = h0[j] * d0 + (f0 / a0) * tg0[j] * (1.0f - d0);
                    h1[j] = h1[j] * d1 + (f1 / a1) * tg1[j] * (1.0f - d1);
                }
            }

            // write g_hB PRE-SWIZZLED per 128-row tile (bulk-copy friendly)
            #pragma unroll
            for (int j = 0; j < 4; j++) {
                int o = o4 + j;
                char* tbase = (char*)g_hB + (size_t)(o >> 7) * B_TILE;
                uint32_t ro = (uint32_t)((o & 127) * 128);
                *(__half*)(tbase + sw128(ro + 2 * lane))
                    = __float2half_rn(SCALING_C * h0[j]);
                *(__half*)(tbase + sw128(ro + 2 * (lane + 32)))
                    = __float2half_rn(SCALING_C * h1[j]);
            }
        }

        __syncthreads();
        if (tid == 0) {
            __threadfence();
            asm volatile("fence.proxy.async;" ::: "memory");
            atomicAdd(&g_liq_done, 1);
        }
    }
}

// ---------------------------------------------------------------------------
extern "C" void kernel_launch(void* const* d_in, const int* in_sizes, int n_in,
                              void* d_out, int out_size)
{
    const float* x       = (const float*)d_in[0];
    const float* lora_A  = (const float*)d_in[1];
    const float* lora_B  = (const float*)d_in[2];
    const float* hidden0 = (const float*)d_in[3];
    const float* W_gate  = (const float*)d_in[4];
    const float* b_gate  = (const float*)d_in[5];
    const float* W_tau   = (const float*)d_in[6];
    const float* b_tau   = (const float*)d_in[7];
    float* out = (float*)d_out;

    int R = in_sizes[5];                 // 64
    int D = in_sizes[1] / R;             // 4096
    int O = in_sizes[2] / R;             // 4096
    int M = in_sizes[0] / D;             // 16384

    const int smemA = 2 * STAGE_BYTES + 1024;        // 54272 (covers liquid + out-phase)

    cudaFuncSetAttribute(fusedAll,
                         cudaFuncAttributeMaxDynamicSharedMemorySize, smemA);

    int nChunk = 64 * (D / 8);           // 32768
    convA_kernel<<<(nChunk + 255) / 256, 256>>>(lora_A, D);

    int nG1 = M / 64;                    // 256
    fusedAll<<<nG1 + NLIQ, 128, smemA>>>(x, lora_B, hidden0,
                                         W_gate, b_gate, W_tau, b_tau,
                                         out, M, D, O, nG1);
}